// round 1
// baseline (speedup 1.0000x reference)
#include <cuda_runtime.h>
#include <math.h>

// Problem constants (fixed by the dataset)
#define NMAX 50000
#define EMAX 800000
#define GMAX 100
#define HD   4
#define CD   64
#define FDIM 256   // HD*CD

// ---------------- scratch (device globals; no allocation allowed) ----------
__device__ float g_h[NMAX * FDIM];      // node features between stages
__device__ float g_xl[NMAX * FDIM];
__device__ float g_xr[NMAX * FDIM];
__device__ float g_out[NMAX * FDIM];    // aggregation accumulator
__device__ float g_alpha[EMAX * HD];    // alpha -> ex (in place)
__device__ float g_amax[NMAX * HD];
__device__ float g_denom[NMAX * HD];
__device__ float g_pool[GMAX * FDIM];
__device__ float g_cnt[GMAX];

// ---------------- helpers ---------------------------------------------------
__device__ __forceinline__ void atomicMaxF(float* addr, float val) {
    int old = __float_as_int(*addr);
    while (__int_as_float(old) < val) {
        int assumed = old;
        old = atomicCAS((int*)addr, assumed, __float_as_int(val));
        if (old == assumed) break;
    }
}

// ---------------- encoder: h = relu(x @ W(8x64) + b) -----------------------
__global__ void enc_kernel(const float* __restrict__ x,
                           const float* __restrict__ W,
                           const float* __restrict__ b, int N) {
    int idx = blockIdx.x * blockDim.x + threadIdx.x;   // n*64 + j
    if (idx >= N * 64) return;
    int n = idx >> 6, j = idx & 63;
    const float* xrow = x + n * 8;
    float acc = b[j];
#pragma unroll
    for (int k = 0; k < 8; ++k) acc = fmaf(xrow[k], W[k * 64 + j], acc);
    g_h[n * 64 + j] = fmaxf(acc, 0.f);
}

// ---------------- xl/xr projections: [N,K] @ [K,256] x2 --------------------
// One block = 256 threads (one output column each) x MB nodes.
template <int K, int MB>
__global__ __launch_bounds__(256) void gemm_xlxr(
    const float* __restrict__ Wl, const float* __restrict__ bl,
    const float* __restrict__ Wr, const float* __restrict__ br, int N) {
    __shared__ float hs[MB * K];
    const int n0 = blockIdx.x * MB;
    const int j  = threadIdx.x;

    for (int idx = threadIdx.x; idx < MB * K; idx += 256) {
        int m = idx / K, k = idx - m * K;
        int n = n0 + m;
        hs[idx] = (n < N) ? g_h[n * K + k] : 0.f;
    }
    __syncthreads();

    float accl[MB], accr[MB];
#pragma unroll
    for (int m = 0; m < MB; ++m) { accl[m] = bl[j]; accr[m] = br[j]; }

    const float4* hs4 = reinterpret_cast<const float4*>(hs);
#pragma unroll 2
    for (int k4 = 0; k4 < K / 4; ++k4) {
        float4 hv[MB];
#pragma unroll
        for (int m = 0; m < MB; ++m) hv[m] = hs4[m * (K / 4) + k4];
#pragma unroll
        for (int kk = 0; kk < 4; ++kk) {
            int k = k4 * 4 + kk;
            float wl = Wl[k * 256 + j];
            float wr = Wr[k * 256 + j];
#pragma unroll
            for (int m = 0; m < MB; ++m) {
                float hvv = (kk == 0) ? hv[m].x : (kk == 1) ? hv[m].y
                            : (kk == 2) ? hv[m].z : hv[m].w;
                accl[m] = fmaf(hvv, wl, accl[m]);
                accr[m] = fmaf(hvv, wr, accr[m]);
            }
        }
    }
#pragma unroll
    for (int m = 0; m < MB; ++m) {
        int n = n0 + m;
        if (n < N) {
            g_xl[n * 256 + j] = accl[m];
            g_xr[n * 256 + j] = accr[m];
        }
    }
}

// ---------------- per-layer init: out=0, amax=-inf, denom=0 ----------------
__global__ void init_layer(int N) {
    int idx = blockIdx.x * blockDim.x + threadIdx.x;
    if (idx < N * FDIM) g_out[idx] = 0.f;
    if (idx < N * HD) {
        g_amax[idx]  = __int_as_float(0xff800000);  // -inf
        g_denom[idx] = 0.f;
    }
}

// ---------------- edge alpha + segment max ---------------------------------
// one warp per edge
__global__ __launch_bounds__(256) void edge_alpha(
    const float* __restrict__ ea, const float* __restrict__ We,
    const float* __restrict__ att, const int* __restrict__ src,
    const int* __restrict__ dst, int E) {
    int e = (blockIdx.x * blockDim.x + threadIdx.x) >> 5;
    int lane = threadIdx.x & 31;
    if (e >= E) return;
    int s = src[e], d = dst[e];
    float w = ea[e];
    const float* xl = g_xl + (long long)s * 256;
    const float* xr = g_xr + (long long)d * 256;

    float sum[4] = {0.f, 0.f, 0.f, 0.f};
#pragma unroll
    for (int i = 0; i < 8; ++i) {
        int j = lane + 32 * i;
        float v = xl[j] + xr[j] + w * We[j];
        v = (v > 0.f) ? v : 0.2f * v;          // leaky_relu 0.2
        sum[i >> 1] = fmaf(v, att[j], sum[i >> 1]);
    }
#pragma unroll
    for (int h = 0; h < 4; ++h) {
#pragma unroll
        for (int off = 16; off; off >>= 1)
            sum[h] += __shfl_xor_sync(0xffffffffu, sum[h], off);
    }
    if (lane == 0) {
#pragma unroll
        for (int h = 0; h < 4; ++h) {
            g_alpha[e * 4 + h] = sum[h];
            atomicMaxF(&g_amax[d * 4 + h], sum[h]);
        }
    }
}

// ---------------- exp + segment sum -----------------------------------------
__global__ void edge_exp(const int* __restrict__ dst, int E) {
    int idx = blockIdx.x * blockDim.x + threadIdx.x;  // e*4 + h
    if (idx >= E * 4) return;
    int e = idx >> 2, h = idx & 3;
    int d = dst[e];
    float ex = expf(g_alpha[idx] - g_amax[d * 4 + h]);
    g_alpha[idx] = ex;
    atomicAdd(&g_denom[d * 4 + h], ex);
}

// ---------------- weighted aggregate: out[dst] += xl[src] * a --------------
__global__ __launch_bounds__(256) void edge_aggregate(
    const int* __restrict__ src, const int* __restrict__ dst, int E) {
    int e = (blockIdx.x * blockDim.x + threadIdx.x) >> 5;
    int lane = threadIdx.x & 31;
    if (e >= E) return;
    int s = src[e], d = dst[e];
    float aa[4];
#pragma unroll
    for (int h = 0; h < 4; ++h)
        aa[h] = g_alpha[e * 4 + h] / (g_denom[d * 4 + h] + 1e-16f);
    const float* xl = g_xl + (long long)s * 256;
    float* out = g_out + (long long)d * 256;
#pragma unroll
    for (int i = 0; i < 8; ++i) {
        int j = lane + 32 * i;
        atomicAdd(&out[j], xl[j] * aa[i >> 1]);
    }
}

// ---------------- bias + relu into g_h --------------------------------------
__global__ void bias_relu(const float* __restrict__ bias, int N) {
    int idx = blockIdx.x * blockDim.x + threadIdx.x;
    if (idx >= N * FDIM) return;
    g_h[idx] = fmaxf(g_out[idx] + bias[idx & 255], 0.f);
}

// ---------------- pooling ----------------------------------------------------
__global__ void pool_init(int G) {
    int idx = blockIdx.x * blockDim.x + threadIdx.x;
    if (idx < G * FDIM) g_pool[idx] = 0.f;
    if (idx < G) g_cnt[idx] = 0.f;
}

__global__ void pool_kernel(const int* __restrict__ batch, int N) {
    int idx = blockIdx.x * blockDim.x + threadIdx.x;
    if (idx >= N * FDIM) return;
    int n = idx >> 8, j = idx & 255;
    int b = batch[n];
    atomicAdd(&g_pool[b * 256 + j], g_h[idx]);
    if (j == 0) atomicAdd(&g_cnt[b], 1.f);
}

// ---------------- head MLP: linear(256->128), LN, relu, linear(128->64), relu
__global__ __launch_bounds__(128) void mlp_kernel(
    const float* __restrict__ p1W, const float* __restrict__ p1b,
    const float* __restrict__ lng, const float* __restrict__ lnb,
    const float* __restrict__ p2W, const float* __restrict__ p2b,
    float* __restrict__ out) {
    int g = blockIdx.x;
    __shared__ float ps[256];
    __shared__ float zs[128];
    __shared__ float red[128];
    float cnt = fmaxf(g_cnt[g], 1.f);
    for (int k = threadIdx.x; k < 256; k += 128)
        ps[k] = g_pool[g * 256 + k] / cnt;
    __syncthreads();

    int j = threadIdx.x;
    float z = p1b[j];
    for (int k = 0; k < 256; ++k) z = fmaf(ps[k], p1W[k * 128 + j], z);

    red[j] = z;
    __syncthreads();
    for (int s = 64; s; s >>= 1) { if (j < s) red[j] += red[j + s]; __syncthreads(); }
    float mu = red[0] * (1.f / 128.f);
    __syncthreads();
    float dz = z - mu;
    red[j] = dz * dz;
    __syncthreads();
    for (int s = 64; s; s >>= 1) { if (j < s) red[j] += red[j + s]; __syncthreads(); }
    float var = red[0] * (1.f / 128.f);
    float zn = dz * rsqrtf(var + 1e-5f) * lng[j] + lnb[j];
    zs[j] = fmaxf(zn, 0.f);
    __syncthreads();

    if (j < 64) {
        float o = p2b[j];
        for (int k = 0; k < 128; ++k) o = fmaf(zs[k], p2W[k * 64 + j], o);
        out[g * 64 + j] = fmaxf(o, 0.f);
    }
}

// ---------------- driver -----------------------------------------------------
static inline void run_gat_layer(int layer, int N, int E,
                                 const int* src, const int* dst,
                                 const float* ea,
                                 const float* Wl, const float* bl,
                                 const float* Wr, const float* br,
                                 const float* We, const float* att,
                                 const float* bias) {
    const int T = 256;
    init_layer<<<(N * FDIM + T - 1) / T, T>>>(N);
    if (layer == 1)
        gemm_xlxr<64, 8><<<(N + 7) / 8, 256>>>(Wl, bl, Wr, br, N);
    else
        gemm_xlxr<256, 8><<<(N + 7) / 8, 256>>>(Wl, bl, Wr, br, N);
    int eblocks = (int)(((long long)E * 32 + T - 1) / T);
    edge_alpha<<<eblocks, T>>>(ea, We, att, src, dst, E);
    edge_exp<<<(E * 4 + T - 1) / T, T>>>(dst, E);
    edge_aggregate<<<eblocks, T>>>(src, dst, E);
    bias_relu<<<(N * FDIM + T - 1) / T, T>>>(bias, N);
}

extern "C" void kernel_launch(void* const* d_in, const int* in_sizes, int n_in,
                              void* d_out, int out_size) {
    const float* x      = (const float*)d_in[0];
    const int*   ei     = (const int*)  d_in[1];
    const float* ea     = (const float*)d_in[2];
    const int*   batch  = (const int*)  d_in[3];
    const float* enc_W  = (const float*)d_in[4];
    const float* enc_b  = (const float*)d_in[5];
    const float* g1_Wl  = (const float*)d_in[6];
    const float* g1_bl  = (const float*)d_in[7];
    const float* g1_Wr  = (const float*)d_in[8];
    const float* g1_br  = (const float*)d_in[9];
    const float* g1_We  = (const float*)d_in[10];
    const float* g1_att = (const float*)d_in[11];
    const float* g1_bias= (const float*)d_in[12];
    const float* g2_Wl  = (const float*)d_in[13];
    const float* g2_bl  = (const float*)d_in[14];
    const float* g2_Wr  = (const float*)d_in[15];
    const float* g2_br  = (const float*)d_in[16];
    const float* g2_We  = (const float*)d_in[17];
    const float* g2_att = (const float*)d_in[18];
    const float* g2_bias= (const float*)d_in[19];
    const float* p1_W   = (const float*)d_in[20];
    const float* p1_b   = (const float*)d_in[21];
    const float* ln_g   = (const float*)d_in[22];
    const float* ln_b   = (const float*)d_in[23];
    const float* p2_W   = (const float*)d_in[24];
    const float* p2_b   = (const float*)d_in[25];

    const int N = in_sizes[3];          // batch vector length = N
    const int E = in_sizes[2];          // edge_attr count (E*1)
    const int G = out_size / 64;

    const int* src = ei;
    const int* dst = ei + E;
    const int T = 256;

    // encoder
    enc_kernel<<<(N * 64 + T - 1) / T, T>>>(x, enc_W, enc_b, N);

    // GATv2 layers
    run_gat_layer(1, N, E, src, dst, ea, g1_Wl, g1_bl, g1_Wr, g1_br,
                  g1_We, g1_att, g1_bias);
    run_gat_layer(2, N, E, src, dst, ea, g2_Wl, g2_bl, g2_Wr, g2_br,
                  g2_We, g2_att, g2_bias);

    // mean pool
    pool_init<<<(G * FDIM + T - 1) / T, T>>>(G);
    pool_kernel<<<(N * FDIM + T - 1) / T, T>>>(batch, N);

    // head MLP
    mlp_kernel<<<G, 128>>>(p1_W, p1_b, ln_g, ln_b, p2_W, p2_b, (float*)d_out);
}

// round 3
// speedup vs baseline: 1.3901x; 1.3901x over previous
#include <cuda_runtime.h>
#include <math.h>

#define NMAX 50000
#define EMAX 800000
#define GMAX 100
#define FDIM 256
#define SMAX 1024   // max in-degree kept in smem (fallback to global beyond)

// ---------------- scratch (device globals) ---------------------------------
__device__ float g_h[NMAX * FDIM];
__device__ float g_xl[NMAX * FDIM];
__device__ float g_xr[NMAX * FDIM];
__device__ float g_alpha[EMAX * 4];          // fallback alpha buffer (CSR order)
__device__ float g_pool[GMAX * FDIM];
__device__ float g_cnt[GMAX];
// CSR
__device__ int   g_deg[NMAX];
__device__ int   g_cur[NMAX];
__device__ int   g_rowptr[NMAX + 1];
__device__ int   g_bsum[64];
__device__ int   g_esrc[EMAX];
__device__ float g_eea[EMAX];

// ---------------- f32x2 helpers ---------------------------------------------
typedef unsigned long long ull;
__device__ __forceinline__ ull fma2(ull a, ull b, ull c) {
    ull d;
    asm("fma.rn.f32x2 %0, %1, %2, %3;" : "=l"(d) : "l"(a), "l"(b), "l"(c));
    return d;
}
__device__ __forceinline__ ull pack2(float lo, float hi) {
    ull o;
    asm("mov.b64 %0, {%1, %2};" : "=l"(o)
        : "r"(__float_as_uint(lo)), "r"(__float_as_uint(hi)));
    return o;
}
__device__ __forceinline__ void unpack2(ull v, float& lo, float& hi) {
    unsigned a, b;
    asm("mov.b64 {%0, %1}, %2;" : "=r"(a), "=r"(b) : "l"(v));
    lo = __uint_as_float(a); hi = __uint_as_float(b);
}

// ---------------- encoder: h = relu(x @ W(8x64) + b) ------------------------
__global__ void enc_kernel(const float* __restrict__ x,
                           const float* __restrict__ W,
                           const float* __restrict__ b, int N) {
    int idx = blockIdx.x * blockDim.x + threadIdx.x;
    if (idx >= N * 64) return;
    int n = idx >> 6, j = idx & 63;
    const float* xrow = x + n * 8;
    float acc = b[j];
#pragma unroll
    for (int k = 0; k < 8; ++k) acc = fmaf(xrow[k], W[k * 64 + j], acc);
    g_h[n * 64 + j] = fmaxf(acc, 0.f);
}

// ---------------- CSR build ---------------------------------------------------
__global__ void csr_zero(int N) {
    int i = blockIdx.x * blockDim.x + threadIdx.x;
    if (i < N) { g_deg[i] = 0; g_cur[i] = 0; }
}
__global__ void csr_hist(const int* __restrict__ dst, int E) {
    int e = blockIdx.x * blockDim.x + threadIdx.x;
    if (e < E) atomicAdd(&g_deg[dst[e]], 1);
}
// chunk = 2048 (256 threads x 8), inclusive scan into rowptr[i+1]
__global__ __launch_bounds__(256) void csr_scan1(int N) {
    __shared__ int s[256];
    int tid = threadIdx.x;
    int base = blockIdx.x * 2048 + tid * 8;
    int v[8]; int run = 0;
#pragma unroll
    for (int i = 0; i < 8; ++i) {
        int d = (base + i < N) ? g_deg[base + i] : 0;
        run += d; v[i] = run;
    }
    s[tid] = run;
    __syncthreads();
    for (int off = 1; off < 256; off <<= 1) {
        int t = (tid >= off) ? s[tid - off] : 0;
        __syncthreads();
        s[tid] += t;
        __syncthreads();
    }
    int pre = s[tid] - run;
#pragma unroll
    for (int i = 0; i < 8; ++i)
        if (base + i < N) g_rowptr[base + i + 1] = pre + v[i];
    if (tid == 255) g_bsum[blockIdx.x] = s[255];
}
__global__ void csr_scan2(int nchunks) {
    if (threadIdx.x == 0) {
        int run = 0;
        for (int c = 0; c < nchunks; ++c) { run += g_bsum[c]; g_bsum[c] = run; }
    }
}
__global__ __launch_bounds__(256) void csr_scan3(int N) {
    int tid = threadIdx.x;
    if (blockIdx.x == 0) {
        if (tid == 0) g_rowptr[0] = 0;
        return;
    }
    int add = g_bsum[blockIdx.x - 1];
    int base = blockIdx.x * 2048 + tid * 8;
#pragma unroll
    for (int i = 0; i < 8; ++i)
        if (base + i < N) g_rowptr[base + i + 1] += add;
}
__global__ void csr_scatter(const int* __restrict__ src,
                            const int* __restrict__ dst,
                            const float* __restrict__ ea, int E) {
    int e = blockIdx.x * blockDim.x + threadIdx.x;
    if (e >= E) return;
    int d = dst[e];
    int pos = g_rowptr[d] + atomicAdd(&g_cur[d], 1);
    g_esrc[pos] = src[e];
    g_eea[pos] = ea[e];
}

// ---------------- xl/xr GEMM with packed f32x2 ------------------------------
// Reads g_h internally (device symbol must NOT be passed from host code).
// block = 256 threads (one output column each), MB=16 nodes per block.
template <int K>
__global__ __launch_bounds__(256) void gemm_xlxr2(
    const float* __restrict__ Wl, const float* __restrict__ bl,
    const float* __restrict__ Wr, const float* __restrict__ br, int N) {
    constexpr int MB = 16, LD = 18;
    __shared__ __align__(16) float hs[K * LD];
    const int n0 = blockIdx.x * MB;
    const int j = threadIdx.x;

    for (int idx = threadIdx.x; idx < MB * K; idx += 256) {
        int m = idx / K, k = idx - m * K;
        int n = n0 + m;
        hs[k * LD + m] = (n < N) ? g_h[(size_t)n * K + k] : 0.f;
    }
    __syncthreads();

    ull accl[8], accr[8];
    float blj = bl[j], brj = br[j];
#pragma unroll
    for (int p = 0; p < 8; ++p) { accl[p] = pack2(blj, blj); accr[p] = pack2(brj, brj); }

#pragma unroll 4
    for (int k = 0; k < K; ++k) {
        float wl = Wl[k * 256 + j];
        float wr = Wr[k * 256 + j];
        ull wl2 = pack2(wl, wl), wr2 = pack2(wr, wr);
        const float* hrow = &hs[k * LD];
#pragma unroll
        for (int p = 0; p < 8; ++p) {
            ull hp = *reinterpret_cast<const ull*>(hrow + 2 * p);
            accl[p] = fma2(hp, wl2, accl[p]);
            accr[p] = fma2(hp, wr2, accr[p]);
        }
    }
#pragma unroll
    for (int p = 0; p < 8; ++p) {
        float l0, l1, r0, r1;
        unpack2(accl[p], l0, l1);
        unpack2(accr[p], r0, r1);
        int n = n0 + 2 * p;
        if (n < N)     { g_xl[(size_t)n * 256 + j] = l0; g_xr[(size_t)n * 256 + j] = r0; }
        if (n + 1 < N) { g_xl[(size_t)(n + 1) * 256 + j] = l1; g_xr[(size_t)(n + 1) * 256 + j] = r1; }
    }
}

// ---------------- fused GATv2 edge phase (per-dst block) --------------------
// alpha -> segment softmax -> weighted aggregate -> bias+relu -> h / pool
template <bool LAST>
__global__ __launch_bounds__(256) void gat_fused(
    const float* __restrict__ We, const float* __restrict__ att,
    const float* __restrict__ bias, const int* __restrict__ batch) {
    __shared__ float xr_s[256], We_s[256], att_s[256], red[256];
    __shared__ int   src_s[SMAX];
    __shared__ float alpha_s[SMAX * 4];

    const int d = blockIdx.x;
    const int tid = threadIdx.x;
    const int start = g_rowptr[d];
    const int deg = g_rowptr[d + 1] - start;

    xr_s[tid] = g_xr[(size_t)d * 256 + tid];
    We_s[tid] = We[tid];
    att_s[tid] = att[tid];
    __syncthreads();

    const bool inm = (deg <= SMAX);
    float* abuf = inm ? alpha_s : &g_alpha[(size_t)start * 4];

    if (deg > 0) {
        // ---- pass A: per-edge alpha (one warp per edge, round-robin) ----
        const int warp = tid >> 5, lane = tid & 31;
        for (int i = warp; i < deg; i += 8) {
            int s = g_esrc[start + i];
            float w = g_eea[start + i];
            if (inm && lane == 0) src_s[i] = s;
            const float* xl = g_xl + (size_t)s * 256;
            float sum[4] = {0.f, 0.f, 0.f, 0.f};
#pragma unroll
            for (int t = 0; t < 8; ++t) {
                int j = lane + 32 * t;
                float v = xl[j] + xr_s[j] + w * We_s[j];
                v = (v > 0.f) ? v : 0.2f * v;
                sum[t >> 1] = fmaf(v, att_s[j], sum[t >> 1]);
            }
#pragma unroll
            for (int h = 0; h < 4; ++h) {
#pragma unroll
                for (int off = 16; off; off >>= 1)
                    sum[h] += __shfl_xor_sync(0xffffffffu, sum[h], off);
            }
            if (lane == 0) {
#pragma unroll
                for (int h = 0; h < 4; ++h) abuf[i * 4 + h] = sum[h];
            }
        }
        __syncthreads();

        // ---- segment softmax (block reductions, no atomics) ----
        const int h = tid >> 6, t6 = tid & 63;
        float m = -__int_as_float(0x7f800000);  // -inf
        for (int i = t6; i < deg; i += 64) m = fmaxf(m, abuf[i * 4 + h]);
        red[tid] = m;
        __syncthreads();
        for (int s = 32; s; s >>= 1) {
            if (t6 < s) red[tid] = fmaxf(red[tid], red[tid + s]);
            __syncthreads();
        }
        float amax = red[h * 64];
        __syncthreads();

        float dsum = 0.f;
        for (int i = t6; i < deg; i += 64) {
            float ex = expf(abuf[i * 4 + h] - amax);
            abuf[i * 4 + h] = ex;
            dsum += ex;
        }
        red[tid] = dsum;
        __syncthreads();
        for (int s = 32; s; s >>= 1) {
            if (t6 < s) red[tid] += red[tid + s];
            __syncthreads();
        }
        float denom = red[h * 64] + 1e-16f;
        __syncthreads();

        // ---- pass B: gather-reduce aggregate (thread = feature) ----
        float acc = 0.f;
#pragma unroll 4
        for (int i = 0; i < deg; ++i) {
            int s = inm ? src_s[i] : g_esrc[start + i];
            acc = fmaf(abuf[i * 4 + h], g_xl[(size_t)s * 256 + tid], acc);
        }
        acc /= denom;

        float val = fmaxf(acc + bias[tid], 0.f);
        if (LAST) atomicAdd(&g_pool[batch[d] * 256 + tid], val);
        else      g_h[(size_t)d * 256 + tid] = val;
    } else {
        float val = fmaxf(bias[tid], 0.f);
        if (LAST) atomicAdd(&g_pool[batch[d] * 256 + tid], val);
        else      g_h[(size_t)d * 256 + tid] = val;
    }
}

// ---------------- pooling setup ----------------------------------------------
__global__ void pool_init(int G) {
    int idx = blockIdx.x * blockDim.x + threadIdx.x;
    if (idx < G * FDIM) g_pool[idx] = 0.f;
    if (idx < G) g_cnt[idx] = 0.f;
}
__global__ void cnt_kernel(const int* __restrict__ batch, int N) {
    int n = blockIdx.x * blockDim.x + threadIdx.x;
    if (n < N) atomicAdd(&g_cnt[batch[n]], 1.f);
}

// ---------------- head MLP ----------------------------------------------------
__global__ __launch_bounds__(128) void mlp_kernel(
    const float* __restrict__ p1W, const float* __restrict__ p1b,
    const float* __restrict__ lng, const float* __restrict__ lnb,
    const float* __restrict__ p2W, const float* __restrict__ p2b,
    float* __restrict__ out) {
    int g = blockIdx.x;
    __shared__ float ps[256];
    __shared__ float zs[128];
    __shared__ float red[128];
    float cnt = fmaxf(g_cnt[g], 1.f);
    for (int k = threadIdx.x; k < 256; k += 128)
        ps[k] = g_pool[g * 256 + k] / cnt;
    __syncthreads();

    int j = threadIdx.x;
    float z = p1b[j];
    for (int k = 0; k < 256; ++k) z = fmaf(ps[k], p1W[k * 128 + j], z);

    red[j] = z;
    __syncthreads();
    for (int s = 64; s; s >>= 1) { if (j < s) red[j] += red[j + s]; __syncthreads(); }
    float mu = red[0] * (1.f / 128.f);
    __syncthreads();
    float dz = z - mu;
    red[j] = dz * dz;
    __syncthreads();
    for (int s = 64; s; s >>= 1) { if (j < s) red[j] += red[j + s]; __syncthreads(); }
    float var = red[0] * (1.f / 128.f);
    float zn = dz * rsqrtf(var + 1e-5f) * lng[j] + lnb[j];
    zs[j] = fmaxf(zn, 0.f);
    __syncthreads();

    if (j < 64) {
        float o = p2b[j];
        for (int k = 0; k < 128; ++k) o = fmaf(zs[k], p2W[k * 64 + j], o);
        out[g * 64 + j] = fmaxf(o, 0.f);
    }
}

// ---------------- driver -------------------------------------------------------
extern "C" void kernel_launch(void* const* d_in, const int* in_sizes, int n_in,
                              void* d_out, int out_size) {
    const float* x      = (const float*)d_in[0];
    const int*   ei     = (const int*)  d_in[1];
    const float* ea     = (const float*)d_in[2];
    const int*   batch  = (const int*)  d_in[3];
    const float* enc_W  = (const float*)d_in[4];
    const float* enc_b  = (const float*)d_in[5];
    const float* g1_Wl  = (const float*)d_in[6];
    const float* g1_bl  = (const float*)d_in[7];
    const float* g1_Wr  = (const float*)d_in[8];
    const float* g1_br  = (const float*)d_in[9];
    const float* g1_We  = (const float*)d_in[10];
    const float* g1_att = (const float*)d_in[11];
    const float* g1_bias= (const float*)d_in[12];
    const float* g2_Wl  = (const float*)d_in[13];
    const float* g2_bl  = (const float*)d_in[14];
    const float* g2_Wr  = (const float*)d_in[15];
    const float* g2_br  = (const float*)d_in[16];
    const float* g2_We  = (const float*)d_in[17];
    const float* g2_att = (const float*)d_in[18];
    const float* g2_bias= (const float*)d_in[19];
    const float* p1_W   = (const float*)d_in[20];
    const float* p1_b   = (const float*)d_in[21];
    const float* ln_g   = (const float*)d_in[22];
    const float* ln_b   = (const float*)d_in[23];
    const float* p2_W   = (const float*)d_in[24];
    const float* p2_b   = (const float*)d_in[25];

    const int N = in_sizes[3];
    const int E = in_sizes[2];
    const int G = out_size / 64;
    const int* src = ei;
    const int* dst = ei + E;
    const int T = 256;

    // encoder
    enc_kernel<<<(N * 64 + T - 1) / T, T>>>(x, enc_W, enc_b, N);

    // CSR build (shared by both layers)
    int nchunks = (N + 2047) / 2048;
    csr_zero<<<(N + T - 1) / T, T>>>(N);
    csr_hist<<<(E + T - 1) / T, T>>>(dst, E);
    csr_scan1<<<nchunks, 256>>>(N);
    csr_scan2<<<1, 32>>>(nchunks);
    csr_scan3<<<nchunks, 256>>>(N);
    csr_scatter<<<(E + T - 1) / T, T>>>(src, dst, ea, E);

    // layer 1
    gemm_xlxr2<64><<<(N + 15) / 16, 256>>>(g1_Wl, g1_bl, g1_Wr, g1_br, N);
    gat_fused<false><<<N, 256>>>(g1_We, g1_att, g1_bias, batch);

    // layer 2 (output fused into pooling)
    gemm_xlxr2<256><<<(N + 15) / 16, 256>>>(g2_Wl, g2_bl, g2_Wr, g2_br, N);
    pool_init<<<(G * FDIM + T - 1) / T, T>>>(G);
    cnt_kernel<<<(N + T - 1) / T, T>>>(batch, N);
    gat_fused<true><<<N, 256>>>(g2_We, g2_att, g2_bias, batch);

    // head MLP
    mlp_kernel<<<G, 128>>>(p1_W, p1_b, ln_g, ln_b, p2_W, p2_b, (float*)d_out);
}

// round 4
// speedup vs baseline: 1.5104x; 1.0866x over previous
#include <cuda_runtime.h>
#include <math.h>

#define NMAX 50000
#define EMAX 800000
#define GMAX 100
#define FDIM 256
#define AMAXS 256   // alpha entries kept in smem (global fallback beyond)
#define CAP   32    // src rows cached in smem during pass A

// ---------------- scratch (device globals) ---------------------------------
__device__ float g_h[NMAX * FDIM];
__device__ float g_xl[NMAX * FDIM];
__device__ float g_xr[NMAX * FDIM];
__device__ float g_alpha[EMAX * 4];
__device__ float g_pool[GMAX * FDIM];
__device__ float g_cnt[GMAX];
__device__ int   g_deg[NMAX];
__device__ int   g_cur[NMAX];
__device__ int   g_rowptr[NMAX + 1];
__device__ int   g_bsum[64];
__device__ int   g_esrc[EMAX];
__device__ float g_eea[EMAX];

// ---------------- f32x2 helpers ---------------------------------------------
typedef unsigned long long ull;
__device__ __forceinline__ ull fma2(ull a, ull b, ull c) {
    ull d;
    asm("fma.rn.f32x2 %0, %1, %2, %3;" : "=l"(d) : "l"(a), "l"(b), "l"(c));
    return d;
}
__device__ __forceinline__ ull pack2(float lo, float hi) {
    ull o;
    asm("mov.b64 %0, {%1, %2};" : "=l"(o)
        : "r"(__float_as_uint(lo)), "r"(__float_as_uint(hi)));
    return o;
}
__device__ __forceinline__ void unpack2(ull v, float& lo, float& hi) {
    unsigned a, b;
    asm("mov.b64 {%0, %1}, %2;" : "=r"(a), "=r"(b) : "l"(v));
    lo = __uint_as_float(a); hi = __uint_as_float(b);
}

// ---------------- encoder + csr zero (fused) ---------------------------------
__global__ void enc_kernel(const float* __restrict__ x,
                           const float* __restrict__ W,
                           const float* __restrict__ b, int N) {
    int idx = blockIdx.x * blockDim.x + threadIdx.x;
    if (idx < N) { g_deg[idx] = 0; g_cur[idx] = 0; }
    if (idx >= N * 64) return;
    int n = idx >> 6, j = idx & 63;
    const float* xrow = x + n * 8;
    float acc = b[j];
#pragma unroll
    for (int k = 0; k < 8; ++k) acc = fmaf(xrow[k], W[k * 64 + j], acc);
    g_h[n * 64 + j] = fmaxf(acc, 0.f);
}

// ---------------- CSR build ---------------------------------------------------
__global__ void csr_hist(const int* __restrict__ dst, int E) {
    int e = blockIdx.x * blockDim.x + threadIdx.x;
    if (e < E) atomicAdd(&g_deg[dst[e]], 1);
}
__global__ __launch_bounds__(256) void csr_scan1(int N) {
    __shared__ int s[256];
    int tid = threadIdx.x;
    int base = blockIdx.x * 2048 + tid * 8;
    int v[8]; int run = 0;
#pragma unroll
    for (int i = 0; i < 8; ++i) {
        int d = (base + i < N) ? g_deg[base + i] : 0;
        run += d; v[i] = run;
    }
    s[tid] = run;
    __syncthreads();
    for (int off = 1; off < 256; off <<= 1) {
        int t = (tid >= off) ? s[tid - off] : 0;
        __syncthreads();
        s[tid] += t;
        __syncthreads();
    }
    int pre = s[tid] - run;
#pragma unroll
    for (int i = 0; i < 8; ++i)
        if (base + i < N) g_rowptr[base + i + 1] = pre + v[i];
    if (tid == 255) g_bsum[blockIdx.x] = s[255];
}
__global__ void csr_scan2(int nchunks) {
    if (threadIdx.x == 0) {
        int run = 0;
        for (int c = 0; c < nchunks; ++c) { run += g_bsum[c]; g_bsum[c] = run; }
    }
}
__global__ __launch_bounds__(256) void csr_scan3(int N) {
    int tid = threadIdx.x;
    if (blockIdx.x == 0) {
        if (tid == 0) g_rowptr[0] = 0;
        return;
    }
    int add = g_bsum[blockIdx.x - 1];
    int base = blockIdx.x * 2048 + tid * 8;
#pragma unroll
    for (int i = 0; i < 8; ++i)
        if (base + i < N) g_rowptr[base + i + 1] += add;
}
__global__ void csr_scatter(const int* __restrict__ src,
                            const int* __restrict__ dst,
                            const float* __restrict__ ea, int E) {
    int e = blockIdx.x * blockDim.x + threadIdx.x;
    if (e >= E) return;
    int d = dst[e];
    int pos = g_rowptr[d] + atomicAdd(&g_cur[d], 1);
    g_esrc[pos] = src[e];
    g_eea[pos] = ea[e];
}

// ---------------- xl/xr GEMM, f32x2, MB=32 -----------------------------------
template <int K>
__global__ __launch_bounds__(256) void gemm_xlxr2(
    const float* __restrict__ Wl, const float* __restrict__ bl,
    const float* __restrict__ Wr, const float* __restrict__ br, int N) {
    constexpr int MB = 32, LD = 34;
    __shared__ __align__(16) float hs[K * LD];
    const int n0 = blockIdx.x * MB;
    const int j = threadIdx.x;

    for (int idx = threadIdx.x; idx < MB * K; idx += 256) {
        int m = idx / K, k = idx - m * K;
        int n = n0 + m;
        hs[k * LD + m] = (n < N) ? g_h[(size_t)n * K + k] : 0.f;
    }
    __syncthreads();

    ull accl[16], accr[16];
    float blj = bl[j], brj = br[j];
#pragma unroll
    for (int p = 0; p < 16; ++p) { accl[p] = pack2(blj, blj); accr[p] = pack2(brj, brj); }

#pragma unroll 4
    for (int k = 0; k < K; ++k) {
        float wl = Wl[k * 256 + j];
        float wr = Wr[k * 256 + j];
        ull wl2 = pack2(wl, wl), wr2 = pack2(wr, wr);
        const float* hrow = &hs[k * LD];
#pragma unroll
        for (int p = 0; p < 16; ++p) {
            ull hp = *reinterpret_cast<const ull*>(hrow + 2 * p);
            accl[p] = fma2(hp, wl2, accl[p]);
            accr[p] = fma2(hp, wr2, accr[p]);
        }
    }
#pragma unroll
    for (int p = 0; p < 16; ++p) {
        float l0, l1, r0, r1;
        unpack2(accl[p], l0, l1);
        unpack2(accr[p], r0, r1);
        int n = n0 + 2 * p;
        if (n < N)     { g_xl[(size_t)n * 256 + j] = l0; g_xr[(size_t)n * 256 + j] = r0; }
        if (n + 1 < N) { g_xl[(size_t)(n + 1) * 256 + j] = l1; g_xr[(size_t)(n + 1) * 256 + j] = r1; }
    }
}

// ---------------- fused GATv2 edge phase (per-dst block) ----------------------
// pass A caches src rows in smem; pass B reuses them (no second gather).
template <bool LAST>
__global__ __launch_bounds__(256) void gat_fused(
    const float* __restrict__ We, const float* __restrict__ att,
    const float* __restrict__ bias, const int* __restrict__ batch) {
    __shared__ float xr_s[256], We_s[256], att_s[256], red[256];
    __shared__ int   src_s[AMAXS];
    __shared__ float alpha_s[AMAXS * 4];
    __shared__ __align__(16) float xlc[CAP * 256];

    const int d = blockIdx.x;
    const int tid = threadIdx.x;
    const int start = g_rowptr[d];
    const int deg = g_rowptr[d + 1] - start;

    xr_s[tid] = g_xr[(size_t)d * 256 + tid];
    We_s[tid] = We[tid];
    att_s[tid] = att[tid];
    __syncthreads();

    if (deg > 0) {
        const bool inm = (deg <= AMAXS);
        float* abuf = inm ? alpha_s : &g_alpha[(size_t)start * 4];

        // ---- pass A: per-edge alpha (warp per edge), cache rows < CAP ----
        const int warp = tid >> 5, lane = tid & 31;
        for (int i = warp; i < deg; i += 8) {
            int s = g_esrc[start + i];
            float w = g_eea[start + i];
            if (inm && lane == 0) src_s[i] = s;
            const float* xl = g_xl + (size_t)s * 256;
            float sum[4] = {0.f, 0.f, 0.f, 0.f};
            bool cache = (i < CAP);
#pragma unroll
            for (int t = 0; t < 8; ++t) {
                int j = lane + 32 * t;
                float xv = xl[j];
                if (cache) xlc[i * 256 + j] = xv;
                float v = xv + xr_s[j] + w * We_s[j];
                v = (v > 0.f) ? v : 0.2f * v;
                sum[t >> 1] = fmaf(v, att_s[j], sum[t >> 1]);
            }
#pragma unroll
            for (int h = 0; h < 4; ++h) {
#pragma unroll
                for (int off = 16; off; off >>= 1)
                    sum[h] += __shfl_xor_sync(0xffffffffu, sum[h], off);
            }
            if (lane == 0) {
#pragma unroll
                for (int h = 0; h < 4; ++h) abuf[i * 4 + h] = sum[h];
            }
        }
        __syncthreads();

        // ---- segment softmax (block reductions) ----
        const int h = tid >> 6, t6 = tid & 63;
        float m = -__int_as_float(0x7f800000);
        for (int i = t6; i < deg; i += 64) m = fmaxf(m, abuf[i * 4 + h]);
        red[tid] = m;
        __syncthreads();
        for (int s = 32; s; s >>= 1) {
            if (t6 < s) red[tid] = fmaxf(red[tid], red[tid + s]);
            __syncthreads();
        }
        float amax = red[h * 64];
        __syncthreads();

        float dsum = 0.f;
        for (int i = t6; i < deg; i += 64) {
            float ex = expf(abuf[i * 4 + h] - amax);
            abuf[i * 4 + h] = ex;
            dsum += ex;
        }
        red[tid] = dsum;
        __syncthreads();
        for (int s = 32; s; s >>= 1) {
            if (t6 < s) red[tid] += red[tid + s];
            __syncthreads();
        }
        float denom = red[h * 64] + 1e-16f;
        __syncthreads();

        // ---- pass B: aggregate from smem cache (global for spill rows) ----
        float acc = 0.f;
        int dc = (deg < CAP) ? deg : CAP;
#pragma unroll 4
        for (int i = 0; i < dc; ++i)
            acc = fmaf(abuf[i * 4 + h], xlc[i * 256 + tid], acc);
        for (int i = CAP; i < deg; ++i) {
            int s = inm ? src_s[i] : g_esrc[start + i];
            acc = fmaf(abuf[i * 4 + h], g_xl[(size_t)s * 256 + tid], acc);
        }
        acc /= denom;

        float val = fmaxf(acc + bias[tid], 0.f);
        if (LAST) atomicAdd(&g_pool[batch[d] * 256 + tid], val);
        else      g_h[(size_t)d * 256 + tid] = val;
    } else {
        float val = fmaxf(bias[tid], 0.f);
        if (LAST) atomicAdd(&g_pool[batch[d] * 256 + tid], val);
        else      g_h[(size_t)d * 256 + tid] = val;
    }
}

// ---------------- pooling setup ------------------------------------------------
__global__ void pool_init(int G) {
    int idx = blockIdx.x * blockDim.x + threadIdx.x;
    if (idx < G * FDIM) g_pool[idx] = 0.f;
    if (idx < G) g_cnt[idx] = 0.f;
}
__global__ void cnt_kernel(const int* __restrict__ batch, int N) {
    int n = blockIdx.x * blockDim.x + threadIdx.x;
    if (n < N) atomicAdd(&g_cnt[batch[n]], 1.f);
}

// ---------------- head MLP -------------------------------------------------------
__global__ __launch_bounds__(128) void mlp_kernel(
    const float* __restrict__ p1W, const float* __restrict__ p1b,
    const float* __restrict__ lng, const float* __restrict__ lnb,
    const float* __restrict__ p2W, const float* __restrict__ p2b,
    float* __restrict__ out) {
    int g = blockIdx.x;
    __shared__ float ps[256];
    __shared__ float zs[128];
    __shared__ float red[128];
    float cnt = fmaxf(g_cnt[g], 1.f);
    for (int k = threadIdx.x; k < 256; k += 128)
        ps[k] = g_pool[g * 256 + k] / cnt;
    __syncthreads();

    int j = threadIdx.x;
    float z = p1b[j];
    for (int k = 0; k < 256; ++k) z = fmaf(ps[k], p1W[k * 128 + j], z);

    red[j] = z;
    __syncthreads();
    for (int s = 64; s; s >>= 1) { if (j < s) red[j] += red[j + s]; __syncthreads(); }
    float mu = red[0] * (1.f / 128.f);
    __syncthreads();
    float dz = z - mu;
    red[j] = dz * dz;
    __syncthreads();
    for (int s = 64; s; s >>= 1) { if (j < s) red[j] += red[j + s]; __syncthreads(); }
    float var = red[0] * (1.f / 128.f);
    float zn = dz * rsqrtf(var + 1e-5f) * lng[j] + lnb[j];
    zs[j] = fmaxf(zn, 0.f);
    __syncthreads();

    if (j < 64) {
        float o = p2b[j];
        for (int k = 0; k < 128; ++k) o = fmaf(zs[k], p2W[k * 64 + j], o);
        out[g * 64 + j] = fmaxf(o, 0.f);
    }
}

// ---------------- driver ----------------------------------------------------------
extern "C" void kernel_launch(void* const* d_in, const int* in_sizes, int n_in,
                              void* d_out, int out_size) {
    const float* x      = (const float*)d_in[0];
    const int*   ei     = (const int*)  d_in[1];
    const float* ea     = (const float*)d_in[2];
    const int*   batch  = (const int*)  d_in[3];
    const float* enc_W  = (const float*)d_in[4];
    const float* enc_b  = (const float*)d_in[5];
    const float* g1_Wl  = (const float*)d_in[6];
    const float* g1_bl  = (const float*)d_in[7];
    const float* g1_Wr  = (const float*)d_in[8];
    const float* g1_br  = (const float*)d_in[9];
    const float* g1_We  = (const float*)d_in[10];
    const float* g1_att = (const float*)d_in[11];
    const float* g1_bias= (const float*)d_in[12];
    const float* g2_Wl  = (const float*)d_in[13];
    const float* g2_bl  = (const float*)d_in[14];
    const float* g2_Wr  = (const float*)d_in[15];
    const float* g2_br  = (const float*)d_in[16];
    const float* g2_We  = (const float*)d_in[17];
    const float* g2_att = (const float*)d_in[18];
    const float* g2_bias= (const float*)d_in[19];
    const float* p1_W   = (const float*)d_in[20];
    const float* p1_b   = (const float*)d_in[21];
    const float* ln_g   = (const float*)d_in[22];
    const float* ln_b   = (const float*)d_in[23];
    const float* p2_W   = (const float*)d_in[24];
    const float* p2_b   = (const float*)d_in[25];

    const int N = in_sizes[3];
    const int E = in_sizes[2];
    const int G = out_size / 64;
    const int* src = ei;
    const int* dst = ei + E;
    const int T = 256;

    // encoder (+ csr zero fused)
    enc_kernel<<<(N * 64 + T - 1) / T, T>>>(x, enc_W, enc_b, N);

    // CSR build
    int nchunks = (N + 2047) / 2048;
    csr_hist<<<(E + T - 1) / T, T>>>(dst, E);
    csr_scan1<<<nchunks, 256>>>(N);
    csr_scan2<<<1, 32>>>(nchunks);
    csr_scan3<<<nchunks, 256>>>(N);
    csr_scatter<<<(E + T - 1) / T, T>>>(src, dst, ea, E);

    // layer 1
    gemm_xlxr2<64><<<(N + 31) / 32, 256>>>(g1_Wl, g1_bl, g1_Wr, g1_br, N);
    gat_fused<false><<<N, 256>>>(g1_We, g1_att, g1_bias, batch);

    // layer 2 (output fused into pooling)
    gemm_xlxr2<256><<<(N + 31) / 32, 256>>>(g2_Wl, g2_bl, g2_Wr, g2_br, N);
    pool_init<<<(G * FDIM + T - 1) / T, T>>>(G);
    cnt_kernel<<<(N + T - 1) / T, T>>>(batch, N);
    gat_fused<true><<<N, 256>>>(g2_We, g2_att, g2_bias, batch);

    // head MLP
    mlp_kernel<<<G, 128>>>(p1_W, p1_b, ln_g, ln_b, p2_W, p2_b, (float*)d_out);
}

// round 5
// speedup vs baseline: 1.7313x; 1.1463x over previous
#include <cuda_runtime.h>
#include <math.h>

#define NMAX 50000
#define EMAX 800000
#define GMAX 100
#define FDIM 256
#define AMAXS 128   // alpha entries kept in smem (global fallback beyond)
#define CAP   32    // src rows cached in smem during pass A

// ---------------- scratch (device globals) ---------------------------------
__device__ float g_h[NMAX * FDIM];
__device__ float g_xl[NMAX * FDIM];
__device__ float g_xr[NMAX * FDIM];
__device__ float g_alpha[EMAX * 4];
__device__ float g_pool[GMAX * FDIM];
__device__ float g_cnt[GMAX];
__device__ int   g_deg[NMAX];
__device__ int   g_cur[NMAX];
__device__ int   g_rowptr[NMAX + 1];
__device__ int   g_esrc[EMAX];
__device__ float g_eea[EMAX];

// ---------------- f32x2 helpers ---------------------------------------------
typedef unsigned long long ull;
__device__ __forceinline__ ull fma2(ull a, ull b, ull c) {
    ull d;
    asm("fma.rn.f32x2 %0, %1, %2, %3;" : "=l"(d) : "l"(a), "l"(b), "l"(c));
    return d;
}
__device__ __forceinline__ ull pack2(float lo, float hi) {
    ull o;
    asm("mov.b64 %0, {%1, %2};" : "=l"(o)
        : "r"(__float_as_uint(lo)), "r"(__float_as_uint(hi)));
    return o;
}
__device__ __forceinline__ void unpack2(ull v, float& lo, float& hi) {
    unsigned a, b;
    asm("mov.b64 {%0, %1}, %2;" : "=r"(a), "=r"(b) : "l"(v));
    lo = __uint_as_float(a); hi = __uint_as_float(b);
}

// ---------------- encoder + zero deg/cur/pool/cnt (fused) --------------------
__global__ void enc_kernel(const float* __restrict__ x,
                           const float* __restrict__ W,
                           const float* __restrict__ b, int N, int G) {
    int idx = blockIdx.x * blockDim.x + threadIdx.x;
    if (idx < N) { g_deg[idx] = 0; g_cur[idx] = 0; }
    if (idx < G * FDIM) g_pool[idx] = 0.f;
    if (idx < G) g_cnt[idx] = 0.f;
    if (idx >= N * 64) return;
    int n = idx >> 6, j = idx & 63;
    const float* xrow = x + n * 8;
    float acc = b[j];
#pragma unroll
    for (int k = 0; k < 8; ++k) acc = fmaf(xrow[k], W[k * 64 + j], acc);
    g_h[n * 64 + j] = fmaxf(acc, 0.f);
}

// ---------------- CSR hist + graph counts ------------------------------------
__global__ void csr_hist(const int* __restrict__ dst,
                         const int* __restrict__ batch, int E, int N) {
    int e = blockIdx.x * blockDim.x + threadIdx.x;
    if (e < E) atomicAdd(&g_deg[dst[e]], 1);
    if (e < N) atomicAdd(&g_cnt[batch[e]], 1.f);
}

// ---------------- single-block scan (N <= 1024*PER) ---------------------------
__global__ __launch_bounds__(1024) void csr_scan(int N) {
    __shared__ int s[1024];
    const int tid = threadIdx.x;
    const int PER = (N + 1023) / 1024;
    const int base = tid * PER;
    int run = 0;
    for (int k = 0; k < PER; ++k) {
        int i = base + k;
        if (i < N) run += g_deg[i];
    }
    s[tid] = run;
    __syncthreads();
    for (int off = 1; off < 1024; off <<= 1) {
        int t = (tid >= off) ? s[tid - off] : 0;
        __syncthreads();
        s[tid] += t;
        __syncthreads();
    }
    int pre = s[tid] - run;
    if (tid == 0) g_rowptr[0] = 0;
    run = pre;
    for (int k = 0; k < PER; ++k) {
        int i = base + k;
        if (i < N) { run += g_deg[i]; g_rowptr[i + 1] = run; }
    }
}

__global__ void csr_scatter(const int* __restrict__ src,
                            const int* __restrict__ dst,
                            const float* __restrict__ ea, int E) {
    int e = blockIdx.x * blockDim.x + threadIdx.x;
    if (e >= E) return;
    int d = dst[e];
    int pos = g_rowptr[d] + atomicAdd(&g_cur[d], 1);
    g_esrc[pos] = src[e];
    g_eea[pos] = ea[e];
}

// ---------------- xl/xr GEMM, f32x2, MB=32 -----------------------------------
template <int K>
__global__ __launch_bounds__(256) void gemm_xlxr2(
    const float* __restrict__ Wl, const float* __restrict__ bl,
    const float* __restrict__ Wr, const float* __restrict__ br, int N) {
    constexpr int MB = 32, LD = 34;
    __shared__ __align__(16) float hs[K * LD];
    const int n0 = blockIdx.x * MB;
    const int j = threadIdx.x;

    for (int idx = threadIdx.x; idx < MB * K; idx += 256) {
        int m = idx / K, k = idx - m * K;
        int n = n0 + m;
        hs[k * LD + m] = (n < N) ? g_h[(size_t)n * K + k] : 0.f;
    }
    __syncthreads();

    ull accl[16], accr[16];
    float blj = bl[j], brj = br[j];
#pragma unroll
    for (int p = 0; p < 16; ++p) { accl[p] = pack2(blj, blj); accr[p] = pack2(brj, brj); }

#pragma unroll 4
    for (int k = 0; k < K; ++k) {
        float wl = Wl[k * 256 + j];
        float wr = Wr[k * 256 + j];
        ull wl2 = pack2(wl, wl), wr2 = pack2(wr, wr);
        const float* hrow = &hs[k * LD];
#pragma unroll
        for (int p = 0; p < 16; ++p) {
            ull hp = *reinterpret_cast<const ull*>(hrow + 2 * p);
            accl[p] = fma2(hp, wl2, accl[p]);
            accr[p] = fma2(hp, wr2, accr[p]);
        }
    }
#pragma unroll
    for (int p = 0; p < 16; ++p) {
        float l0, l1, r0, r1;
        unpack2(accl[p], l0, l1);
        unpack2(accr[p], r0, r1);
        int n = n0 + 2 * p;
        if (n < N)     { g_xl[(size_t)n * 256 + j] = l0; g_xr[(size_t)n * 256 + j] = r0; }
        if (n + 1 < N) { g_xl[(size_t)(n + 1) * 256 + j] = l1; g_xr[(size_t)(n + 1) * 256 + j] = r1; }
    }
}

// ---------------- fused GATv2 edge phase (per-dst block) ----------------------
// float4 gathers, warp-per-head softmax (2 block syncs total)
template <bool LAST>
__global__ __launch_bounds__(256) void gat_fused(
    const float* __restrict__ We, const float* __restrict__ att,
    const float* __restrict__ bias, const int* __restrict__ batch) {
    __shared__ __align__(16) float4 xr4[64], We4[64], att4[64];
    __shared__ float denom_s[4];
    __shared__ int   src_s[AMAXS];
    __shared__ float alpha_s[AMAXS * 4];
    __shared__ __align__(16) float4 xlc4[CAP * 64];

    const int d = blockIdx.x;
    const int tid = threadIdx.x;
    const int start = g_rowptr[d];
    const int deg = g_rowptr[d + 1] - start;

    if (tid < 64)        xr4[tid]       = reinterpret_cast<const float4*>(g_xr + (size_t)d * 256)[tid];
    else if (tid < 128)  We4[tid - 64]  = reinterpret_cast<const float4*>(We)[tid - 64];
    else if (tid < 192)  att4[tid - 128]= reinterpret_cast<const float4*>(att)[tid - 128];
    __syncthreads();

    if (deg > 0) {
        const bool inm = (deg <= AMAXS);
        float* abuf = inm ? alpha_s : &g_alpha[(size_t)start * 4];

        // ---- pass A: warp per edge; two float4 per lane; cache rows < CAP ----
        const int warp = tid >> 5, lane = tid & 31;
        for (int i = warp; i < deg; i += 8) {
            int s = g_esrc[start + i];
            float w = g_eea[start + i];
            if (inm && lane == 0) src_s[i] = s;
            const float4* xl4 = reinterpret_cast<const float4*>(g_xl + (size_t)s * 256);
            float4 a0 = xl4[lane];
            float4 a1 = xl4[lane + 32];
            if (i < CAP) { xlc4[i * 64 + lane] = a0; xlc4[i * 64 + lane + 32] = a1; }

            float4 x0 = xr4[lane],      e0 = We4[lane],      t0 = att4[lane];
            float4 x1 = xr4[lane + 32], e1 = We4[lane + 32], t1 = att4[lane + 32];

            float v, p0, p1;
            v = a0.x + x0.x + w * e0.x; v = (v > 0.f) ? v : 0.2f * v; p0 = v * t0.x;
            v = a0.y + x0.y + w * e0.y; v = (v > 0.f) ? v : 0.2f * v; p0 = fmaf(v, t0.y, p0);
            v = a0.z + x0.z + w * e0.z; v = (v > 0.f) ? v : 0.2f * v; p0 = fmaf(v, t0.z, p0);
            v = a0.w + x0.w + w * e0.w; v = (v > 0.f) ? v : 0.2f * v; p0 = fmaf(v, t0.w, p0);
            v = a1.x + x1.x + w * e1.x; v = (v > 0.f) ? v : 0.2f * v; p1 = v * t1.x;
            v = a1.y + x1.y + w * e1.y; v = (v > 0.f) ? v : 0.2f * v; p1 = fmaf(v, t1.y, p1);
            v = a1.z + x1.z + w * e1.z; v = (v > 0.f) ? v : 0.2f * v; p1 = fmaf(v, t1.z, p1);
            v = a1.w + x1.w + w * e1.w; v = (v > 0.f) ? v : 0.2f * v; p1 = fmaf(v, t1.w, p1);

            // reduce within 16-lane half-warps: lanes 0-15 -> head0(p0)/head2(p1),
            // lanes 16-31 -> head1(p0)/head3(p1)
#pragma unroll
            for (int off = 8; off; off >>= 1) {
                p0 += __shfl_xor_sync(0xffffffffu, p0, off);
                p1 += __shfl_xor_sync(0xffffffffu, p1, off);
            }
            if ((lane & 15) == 0) {
                int hh = lane >> 4;
                abuf[i * 4 + hh]     = p0;
                abuf[i * 4 + 2 + hh] = p1;
            }
        }
        __syncthreads();

        // ---- softmax: warp h handles head h (shuffle-only reductions) ----
        if (warp < 4) {
            const int h = warp;
            float m = -__int_as_float(0x7f800000);
            for (int i = lane; i < deg; i += 32) m = fmaxf(m, abuf[i * 4 + h]);
#pragma unroll
            for (int off = 16; off; off >>= 1)
                m = fmaxf(m, __shfl_xor_sync(0xffffffffu, m, off));
            float sm = 0.f;
            for (int i = lane; i < deg; i += 32) {
                float ex = expf(abuf[i * 4 + h] - m);
                abuf[i * 4 + h] = ex;
                sm += ex;
            }
#pragma unroll
            for (int off = 16; off; off >>= 1)
                sm += __shfl_xor_sync(0xffffffffu, sm, off);
            if (lane == 0) denom_s[h] = sm + 1e-16f;
        }
        __syncthreads();

        // ---- pass B: aggregate (thread = feature), smem cache + spill ----
        const int h = tid >> 6;
        const float* xlc = reinterpret_cast<const float*>(xlc4);
        float acc = 0.f;
        int dc = (deg < CAP) ? deg : CAP;
#pragma unroll 4
        for (int i = 0; i < dc; ++i)
            acc = fmaf(abuf[i * 4 + h], xlc[i * 256 + tid], acc);
        for (int i = CAP; i < deg; ++i) {
            int s = inm ? src_s[i] : g_esrc[start + i];
            acc = fmaf(abuf[i * 4 + h], g_xl[(size_t)s * 256 + tid], acc);
        }
        acc /= denom_s[h];

        float val = fmaxf(acc + bias[tid], 0.f);
        if (LAST) atomicAdd(&g_pool[batch[d] * 256 + tid], val);
        else      g_h[(size_t)d * 256 + tid] = val;
    } else {
        float val = fmaxf(bias[tid], 0.f);
        if (LAST) atomicAdd(&g_pool[batch[d] * 256 + tid], val);
        else      g_h[(size_t)d * 256 + tid] = val;
    }
}

// ---------------- head MLP -------------------------------------------------------
__global__ __launch_bounds__(128) void mlp_kernel(
    const float* __restrict__ p1W, const float* __restrict__ p1b,
    const float* __restrict__ lng, const float* __restrict__ lnb,
    const float* __restrict__ p2W, const float* __restrict__ p2b,
    float* __restrict__ out) {
    int g = blockIdx.x;
    __shared__ float ps[256];
    __shared__ float zs[128];
    __shared__ float red[128];
    float cnt = fmaxf(g_cnt[g], 1.f);
    for (int k = threadIdx.x; k < 256; k += 128)
        ps[k] = g_pool[g * 256 + k] / cnt;
    __syncthreads();

    int j = threadIdx.x;
    float z = p1b[j];
    for (int k = 0; k < 256; ++k) z = fmaf(ps[k], p1W[k * 128 + j], z);

    red[j] = z;
    __syncthreads();
    for (int s = 64; s; s >>= 1) { if (j < s) red[j] += red[j + s]; __syncthreads(); }
    float mu = red[0] * (1.f / 128.f);
    __syncthreads();
    float dz = z - mu;
    red[j] = dz * dz;
    __syncthreads();
    for (int s = 64; s; s >>= 1) { if (j < s) red[j] += red[j + s]; __syncthreads(); }
    float var = red[0] * (1.f / 128.f);
    float zn = dz * rsqrtf(var + 1e-5f) * lng[j] + lnb[j];
    zs[j] = fmaxf(zn, 0.f);
    __syncthreads();

    if (j < 64) {
        float o = p2b[j];
        for (int k = 0; k < 128; ++k) o = fmaf(zs[k], p2W[k * 64 + j], o);
        out[g * 64 + j] = fmaxf(o, 0.f);
    }
}

// ---------------- driver ----------------------------------------------------------
extern "C" void kernel_launch(void* const* d_in, const int* in_sizes, int n_in,
                              void* d_out, int out_size) {
    const float* x      = (const float*)d_in[0];
    const int*   ei     = (const int*)  d_in[1];
    const float* ea     = (const float*)d_in[2];
    const int*   batch  = (const int*)  d_in[3];
    const float* enc_W  = (const float*)d_in[4];
    const float* enc_b  = (const float*)d_in[5];
    const float* g1_Wl  = (const float*)d_in[6];
    const float* g1_bl  = (const float*)d_in[7];
    const float* g1_Wr  = (const float*)d_in[8];
    const float* g1_br  = (const float*)d_in[9];
    const float* g1_We  = (const float*)d_in[10];
    const float* g1_att = (const float*)d_in[11];
    const float* g1_bias= (const float*)d_in[12];
    const float* g2_Wl  = (const float*)d_in[13];
    const float* g2_bl  = (const float*)d_in[14];
    const float* g2_Wr  = (const float*)d_in[15];
    const float* g2_br  = (const float*)d_in[16];
    const float* g2_We  = (const float*)d_in[17];
    const float* g2_att = (const float*)d_in[18];
    const float* g2_bias= (const float*)d_in[19];
    const float* p1_W   = (const float*)d_in[20];
    const float* p1_b   = (const float*)d_in[21];
    const float* ln_g   = (const float*)d_in[22];
    const float* ln_b   = (const float*)d_in[23];
    const float* p2_W   = (const float*)d_in[24];
    const float* p2_b   = (const float*)d_in[25];

    const int N = in_sizes[3];
    const int E = in_sizes[2];
    const int G = out_size / 64;
    const int* src = ei;
    const int* dst = ei + E;
    const int T = 256;

    // 1: encoder (+ zero deg/cur/pool/cnt)
    enc_kernel<<<(N * 64 + T - 1) / T, T>>>(x, enc_W, enc_b, N, G);
    // 2: degree histogram (+ batch counts)
    csr_hist<<<(E + T - 1) / T, T>>>(dst, batch, E, N);
    // 3: rowptr scan (single block)
    csr_scan<<<1, 1024>>>(N);
    // 4: edge scatter into CSR
    csr_scatter<<<(E + T - 1) / T, T>>>(src, dst, ea, E);

    // 5: layer-1 projections
    gemm_xlxr2<64><<<(N + 31) / 32, 256>>>(g1_Wl, g1_bl, g1_Wr, g1_br, N);
    // 6: layer-1 fused GAT  (<- ncu -s 5 -c 1 profiles this launch)
    gat_fused<false><<<N, 256>>>(g1_We, g1_att, g1_bias, batch);

    // 7: layer-2 projections
    gemm_xlxr2<256><<<(N + 31) / 32, 256>>>(g2_Wl, g2_bl, g2_Wr, g2_br, N);
    // 8: layer-2 fused GAT, output into pool
    gat_fused<true><<<N, 256>>>(g2_We, g2_att, g2_bias, batch);

    // 9: head MLP
    mlp_kernel<<<G, 128>>>(p1_W, p1_b, ln_g, ln_b, p2_W, p2_b, (float*)d_out);
}